// round 14
// baseline (speedup 1.0000x reference)
#include <cuda_runtime.h>
#include <cuda_fp16.h>
#include <cstdint>

// Problem constants
#define M_DIM   32
#define K_DIM   8192
#define N_DIM   8192
#define GROUP   128

#define NTILE   256                    // n-columns per CTA
#define SPLITS  8                      // split-K factor
#define KSPLIT  (K_DIM / SPLITS)       // 1024 k per CTA
#define NUM_KT  (KSPLIT / GROUP)       // 8 k-tiles of 128
#define THREADS 256                    // 8 warps, each owns 32 n-columns
#define NTILES  (N_DIM / NTILE)        // 32

// Activation SMEM tile: [32 m][136 halves] per buffer, k-PERMUTED per octet:
//   octet o of row m at halves [o*8..o*8+7] = (v0,v4,v1,v5,v2,v6,v3,v7)
// row stride 272 B == 16 mod 128 -> b-frag banks 16*lane4 + 4*(lane&3): all distinct
#define APITCH  136
#define ABUF_HALVES (32 * APITCH)      // 4352 halves = 8704 B per buffer

// Split-K partials: [SPLITS][32][8192] fp32 (8 MB static device scratch)
__device__ float g_partial[SPLITS * M_DIM * N_DIM];

// lop3: (a & b) | c  -> immLut 0xEA
static __device__ __forceinline__ uint32_t lop3_and_or(uint32_t a, uint32_t b, uint32_t c) {
    uint32_t d;
    asm("lop3.b32 %0, %1, %2, %3, 0xEA;" : "=r"(d) : "r"(a), "r"(b), "r"(c));
    return d;
}

// Uniform per-lane dequant: lane j = lane&3 extracts nibble pair (j, j+4) of qword.
//  j even: h = ((q>>sh) & 0x000F000F) | 0x64006400 ; v = h*1 + (-1032)    = q-8 (exact)
//  j odd:  h = ((q>>sh) & 0x00F000F0) | 0x64006400 ; v = h*(1/16) + (-72) = q-8 (exact)
// then r = v * s (one fp16 rounding).
static __device__ __forceinline__ uint32_t dq2(uint32_t q, uint32_t sh, uint32_t mask,
                                               uint32_t cm2, uint32_t ca2, uint32_t s2) {
    uint32_t u = q >> sh;
    uint32_t h = lop3_and_or(u, mask, 0x64006400u);
    half2 v = __hfma2(*reinterpret_cast<half2*>(&h),
                      *reinterpret_cast<half2*>(&cm2),
                      *reinterpret_cast<half2*>(&ca2));
    half2 r = __hmul2(v, *reinterpret_cast<half2*>(&s2));
    return *reinterpret_cast<uint32_t*>(&r);
}

static __device__ __forceinline__ void mma_16816(float& d0, float& d1, float& d2, float& d3,
                                                 uint32_t a0, uint32_t a1, uint32_t a2,
                                                 uint32_t a3, uint32_t b0, uint32_t b1) {
    asm volatile(
        "mma.sync.aligned.m16n8k16.row.col.f32.f16.f16.f32 "
        "{%0,%1,%2,%3}, {%4,%5,%6,%7}, {%8,%9}, {%0,%1,%2,%3};\n"
        : "+f"(d0), "+f"(d1), "+f"(d2), "+f"(d3)
        : "r"(a0), "r"(a1), "r"(a2), "r"(a3), "r"(b0), "r"(b1));
}

__global__ void __launch_bounds__(THREADS, 2)
marlin_w4a16_main(const float* __restrict__ A, const int* __restrict__ qw,
                  const float* __restrict__ scales) {
    __shared__ __align__(16) half as2[2][ABUF_HALVES];

    const int tid   = threadIdx.x;
    const int lane  = tid & 31;
    const int warp  = tid >> 5;            // 0..7
    const int lane4 = lane >> 2;           // 0..7

    // per-lane dequant constants
    const uint32_t sh   = (lane & 2) << 2;                        // 0 or 8
    const uint32_t mask = (lane & 1) ? 0x00F000F0u : 0x000F000Fu;
    const uint32_t cm2  = (lane & 1) ? 0x2C002C00u : 0x3C003C00u; // 1/16 : 1.0
    const uint32_t ca2  = (lane & 1) ? 0xD480D480u : 0xE408E408u; // -72 : -1032

    const int nbase = blockIdx.x * NTILE;  // CTA n-range
    const int split = blockIdx.y;          // k-split index
    const int k0    = split * KSPLIT;
    const int c0    = nbase + warp * 32 + lane4;   // this thread's frag-row-0 column

    // Staging coords: 32 rows x 8 threads/row, 2 octets (16 k) each
    const int sm = tid >> 3;               // 0..31 (m row)
    const int so = tid & 7;                // 0..7
    const float* a_row = A + (size_t)sm * K_DIM + k0;

    // Accumulators: [a-frag f(2)][m-tile t(4)][4]
    float acc[2][4][4];
#pragma unroll
    for (int f = 0; f < 2; f++)
#pragma unroll
        for (int t = 0; t < 4; t++)
#pragma unroll
            for (int r = 0; r < 4; r++) acc[f][t][r] = 0.0f;

    const int* qcol = qw + c0;             // + row*N_DIM per k-row-of-8

#pragma unroll 1
    for (int kt = 0; kt < NUM_KT; kt++) {
        const int buf = kt & 1;

        // ---- stage A[0:32][kt*128 .. +128): fp32 -> fp16, k-permuted octets ----
        {
            const float* src = a_row + kt * GROUP;
            half* dst = &as2[buf][sm * APITCH];
#pragma unroll
            for (int jo = 0; jo < 2; jo++) {
                const int o = so + 8 * jo;     // octet 0..15
                float4 va = *reinterpret_cast<const float4*>(src + o * 8);
                float4 vb = *reinterpret_cast<const float4*>(src + o * 8 + 4);
                half2 p0 = __floats2half2_rn(va.x, vb.x);   // (v0, v4)
                half2 p1 = __floats2half2_rn(va.y, vb.y);   // (v1, v5)
                half2 p2 = __floats2half2_rn(va.z, vb.z);   // (v2, v6)
                half2 p3 = __floats2half2_rn(va.w, vb.w);   // (v3, v7)
                uint4 pk;
                pk.x = *reinterpret_cast<uint32_t*>(&p0);
                pk.y = *reinterpret_cast<uint32_t*>(&p1);
                pk.z = *reinterpret_cast<uint32_t*>(&p2);
                pk.w = *reinterpret_cast<uint32_t*>(&p3);
                *reinterpret_cast<uint4*>(dst + o * 8) = pk;
            }
        }
        __syncthreads();

        // ---- per-group scales for this thread's 4 n-columns ----
        uint32_t s2[4];
        {
            const float* sp = scales + (size_t)(split * NUM_KT + kt) * N_DIM + c0;
#pragma unroll
            for (int r = 0; r < 4; r++) {
                half hs = __float2half_rn(sp[r * 8]);
                half2 p = __halves2half2(hs, hs);
                s2[r] = *reinterpret_cast<uint32_t*>(&p);
            }
        }

        const int qrow0 = (k0 + kt * GROUP) >> 3;   // first k-row-of-8 in this tile

        // ---- 8 chunks of k16 (fully unrolled: ptxas batches the 64 LDGs) ----
        // qweight is streamed exactly once chip-wide: load with .cs (evict-first)
        // so it does NOT evict the L2-resident partials/A/scales.
#pragma unroll
        for (int ch = 0; ch < 8; ch++) {
            const int* qr0 = qcol + (size_t)(qrow0 + 2 * ch) * N_DIM;
            const int* qr1 = qr0 + N_DIM;
            // W loads (4-lane broadcast each): rows {2ch, 2ch+1} x col offsets {0,8,16,24}
            uint32_t q00 = (uint32_t)__ldcs(qr0),      q01 = (uint32_t)__ldcs(qr0 + 8);
            uint32_t q02 = (uint32_t)__ldcs(qr0 + 16), q03 = (uint32_t)__ldcs(qr0 + 24);
            uint32_t q10 = (uint32_t)__ldcs(qr1),      q11 = (uint32_t)__ldcs(qr1 + 8);
            uint32_t q12 = (uint32_t)__ldcs(qr1 + 16), q13 = (uint32_t)__ldcs(qr1 + 24);

            // a-frags (dequant straight into fragment registers)
            uint32_t a[2][4];
            a[0][0] = dq2(q00, sh, mask, cm2, ca2, s2[0]);  // row n,    k pair j
            a[0][1] = dq2(q01, sh, mask, cm2, ca2, s2[1]);  // row n+8
            a[0][2] = dq2(q10, sh, mask, cm2, ca2, s2[0]);  // row n,    k pair j+8
            a[0][3] = dq2(q11, sh, mask, cm2, ca2, s2[1]);  // row n+8
            a[1][0] = dq2(q02, sh, mask, cm2, ca2, s2[2]);
            a[1][1] = dq2(q03, sh, mask, cm2, ca2, s2[3]);
            a[1][2] = dq2(q12, sh, mask, cm2, ca2, s2[2]);
            a[1][3] = dq2(q13, sh, mask, cm2, ca2, s2[3]);

            // b-frags: permuted-k pairs, m = 8t + lane4, pair j = lane&3
            const half* bb = &as2[buf][(size_t)(ch * 16 + (lane & 3) * 2)];
            uint32_t b[4][2];
#pragma unroll
            for (int t = 0; t < 4; t++) {
                const half* bp = bb + (size_t)(8 * t + lane4) * APITCH;
                b[t][0] = *reinterpret_cast<const uint32_t*>(bp);       // octet 2ch
                b[t][1] = *reinterpret_cast<const uint32_t*>(bp + 8);   // octet 2ch+1
            }

#pragma unroll
            for (int f = 0; f < 2; f++)
#pragma unroll
                for (int t = 0; t < 4; t++)
                    mma_16816(acc[f][t][0], acc[f][t][1], acc[f][t][2], acc[f][t][3],
                              a[f][0], a[f][1], a[f][2], a[f][3], b[t][0], b[t][1]);
        }
    }

    // ---- epilogue: write split partials, D[n][m] frag -> partial[split][m][n] ----
    float* pbase = g_partial + (size_t)split * M_DIM * N_DIM;
#pragma unroll
    for (int f = 0; f < 2; f++) {
        const int n_r = nbase + warp * 32 + 16 * f + lane4;
#pragma unroll
        for (int t = 0; t < 4; t++) {
            const int m_c = 8 * t + 2 * (lane & 3);
            float* p = pbase + (size_t)m_c * N_DIM + n_r;
            p[0]         = acc[f][t][0];   // (n_r,   m_c)
            p[N_DIM]     = acc[f][t][1];   // (n_r,   m_c+1)
            p[8]         = acc[f][t][2];   // (n_r+8, m_c)
            p[N_DIM + 8] = acc[f][t][3];   // (n_r+8, m_c+1)
        }
    }
}

__global__ void __launch_bounds__(256)
marlin_w4a16_reduce(const float* __restrict__ bias, float* __restrict__ out) {
    const int v = blockIdx.x * 256 + threadIdx.x;   // float4 index, n fastest
    const int e = v * 4;
    const int n = e & (N_DIM - 1);
    float4 s = make_float4(0.f, 0.f, 0.f, 0.f);
#pragma unroll
    for (int sp = 0; sp < SPLITS; sp++) {
        float4 p = *reinterpret_cast<const float4*>(
            &g_partial[(size_t)sp * (M_DIM * N_DIM) + e]);
        s.x += p.x; s.y += p.y; s.z += p.z; s.w += p.w;
    }
    float4 b = *reinterpret_cast<const float4*>(bias + n);
    s.x += b.x; s.y += b.y; s.z += b.z; s.w += b.w;
    *reinterpret_cast<float4*>(out + e) = s;
}

extern "C" void kernel_launch(void* const* d_in, const int* in_sizes, int n_in,
                              void* d_out, int out_size) {
    const float* A      = (const float*)d_in[0];
    const int*   qw     = (const int*)d_in[1];
    const float* scales = (const float*)d_in[2];
    const float* bias   = (const float*)d_in[3];
    float* out = (float*)d_out;

    dim3 grid(NTILES, SPLITS);
    marlin_w4a16_main<<<grid, THREADS>>>(A, qw, scales);
    marlin_w4a16_reduce<<<(M_DIM * N_DIM) / (256 * 4), 256>>>(bias, out);
}

// round 15
// speedup vs baseline: 1.7405x; 1.7405x over previous
#include <cuda_runtime.h>
#include <cuda_fp16.h>
#include <cstdint>

// Problem constants
#define M_DIM   32
#define K_DIM   8192
#define N_DIM   8192
#define GROUP   128

#define NTILE   256                    // n-columns per CTA
#define SPLITS  8                      // split-K factor
#define KSPLIT  (K_DIM / SPLITS)       // 1024 k per CTA
#define NUM_KT  (KSPLIT / GROUP)       // 8 k-tiles of 128
#define THREADS 256                    // 8 warps, each owns 32 n-columns
#define NTILES  (N_DIM / NTILE)        // 32

// Activation SMEM tile: [32 m][136 halves] per buffer, k-PERMUTED per octet:
//   octet o of row m at halves [o*8..o*8+7] = (v0,v4,v1,v5,v2,v6,v3,v7)
// row stride 272 B == 16 mod 128 -> b-frag banks 16*lane4 + 4*(lane&3): all distinct
#define APITCH  136
#define ABUF_HALVES (32 * APITCH)      // 4352 halves = 8704 B per buffer

// Split-K partials: [SPLITS][32][8192] fp32 (8 MB static device scratch)
__device__ float g_partial[SPLITS * M_DIM * N_DIM];

// lop3: (a & b) | c  -> immLut 0xEA
static __device__ __forceinline__ uint32_t lop3_and_or(uint32_t a, uint32_t b, uint32_t c) {
    uint32_t d;
    asm("lop3.b32 %0, %1, %2, %3, 0xEA;" : "=r"(d) : "r"(a), "r"(b), "r"(c));
    return d;
}

// Uniform per-lane dequant: lane j = lane&3 extracts nibble pair (j, j+4) of qword.
//  j even: h = ((q>>sh) & 0x000F000F) | 0x64006400 ; v = h*1 + (-1032)    = q-8 (exact)
//  j odd:  h = ((q>>sh) & 0x00F000F0) | 0x64006400 ; v = h*(1/16) + (-72) = q-8 (exact)
// then r = v * s (one fp16 rounding).
static __device__ __forceinline__ uint32_t dq2(uint32_t q, uint32_t sh, uint32_t mask,
                                               uint32_t cm2, uint32_t ca2, uint32_t s2) {
    uint32_t u = q >> sh;
    uint32_t h = lop3_and_or(u, mask, 0x64006400u);
    half2 v = __hfma2(*reinterpret_cast<half2*>(&h),
                      *reinterpret_cast<half2*>(&cm2),
                      *reinterpret_cast<half2*>(&ca2));
    half2 r = __hmul2(v, *reinterpret_cast<half2*>(&s2));
    return *reinterpret_cast<uint32_t*>(&r);
}

static __device__ __forceinline__ void mma_16816(float& d0, float& d1, float& d2, float& d3,
                                                 uint32_t a0, uint32_t a1, uint32_t a2,
                                                 uint32_t a3, uint32_t b0, uint32_t b1) {
    asm volatile(
        "mma.sync.aligned.m16n8k16.row.col.f32.f16.f16.f32 "
        "{%0,%1,%2,%3}, {%4,%5,%6,%7}, {%8,%9}, {%0,%1,%2,%3};\n"
        : "+f"(d0), "+f"(d1), "+f"(d2), "+f"(d3)
        : "r"(a0), "r"(a1), "r"(a2), "r"(a3), "r"(b0), "r"(b1));
}

__global__ void __launch_bounds__(THREADS, 2)
marlin_w4a16_main(const float* __restrict__ A, const int* __restrict__ qw,
                  const float* __restrict__ scales) {
    __shared__ __align__(16) half as2[2][ABUF_HALVES];

    const int tid   = threadIdx.x;
    const int lane  = tid & 31;
    const int warp  = tid >> 5;            // 0..7
    const int lane4 = lane >> 2;           // 0..7

    // per-lane dequant constants
    const uint32_t sh   = (lane & 2) << 2;                        // 0 or 8
    const uint32_t mask = (lane & 1) ? 0x00F000F0u : 0x000F000Fu;
    const uint32_t cm2  = (lane & 1) ? 0x2C002C00u : 0x3C003C00u; // 1/16 : 1.0
    const uint32_t ca2  = (lane & 1) ? 0xD480D480u : 0xE408E408u; // -72 : -1032

    const int nbase = blockIdx.x * NTILE;  // CTA n-range
    const int split = blockIdx.y;          // k-split index
    const int k0    = split * KSPLIT;
    const int c0    = nbase + warp * 32 + lane4;   // this thread's frag-row-0 column

    // Staging coords: 32 rows x 8 threads/row, 2 octets (16 k) each
    const int sm = tid >> 3;               // 0..31 (m row)
    const int so = tid & 7;                // 0..7
    const float* a_row = A + (size_t)sm * K_DIM + k0;

    // Accumulators: [a-frag f(2)][m-tile t(4)][4]
    float acc[2][4][4];
#pragma unroll
    for (int f = 0; f < 2; f++)
#pragma unroll
        for (int t = 0; t < 4; t++)
#pragma unroll
            for (int r = 0; r < 4; r++) acc[f][t][r] = 0.0f;

    const int* qcol = qw + c0;             // + row*N_DIM per k-row-of-8

#pragma unroll 1
    for (int kt = 0; kt < NUM_KT; kt++) {
        const int buf = kt & 1;

        // ---- stage A[0:32][kt*128 .. +128): fp32 -> fp16, k-permuted octets ----
        {
            const float* src = a_row + kt * GROUP;
            half* dst = &as2[buf][sm * APITCH];
#pragma unroll
            for (int jo = 0; jo < 2; jo++) {
                const int o = so + 8 * jo;     // octet 0..15
                float4 va = *reinterpret_cast<const float4*>(src + o * 8);
                float4 vb = *reinterpret_cast<const float4*>(src + o * 8 + 4);
                half2 p0 = __floats2half2_rn(va.x, vb.x);   // (v0, v4)
                half2 p1 = __floats2half2_rn(va.y, vb.y);   // (v1, v5)
                half2 p2 = __floats2half2_rn(va.z, vb.z);   // (v2, v6)
                half2 p3 = __floats2half2_rn(va.w, vb.w);   // (v3, v7)
                uint4 pk;
                pk.x = *reinterpret_cast<uint32_t*>(&p0);
                pk.y = *reinterpret_cast<uint32_t*>(&p1);
                pk.z = *reinterpret_cast<uint32_t*>(&p2);
                pk.w = *reinterpret_cast<uint32_t*>(&p3);
                *reinterpret_cast<uint4*>(dst + o * 8) = pk;
            }
        }
        __syncthreads();

        // ---- per-group scales for this thread's 4 n-columns ----
        uint32_t s2[4];
        {
            const float* sp = scales + (size_t)(split * NUM_KT + kt) * N_DIM + c0;
#pragma unroll
            for (int r = 0; r < 4; r++) {
                half hs = __float2half_rn(sp[r * 8]);
                half2 p = __halves2half2(hs, hs);
                s2[r] = *reinterpret_cast<uint32_t*>(&p);
            }
        }

        const int qrow0 = (k0 + kt * GROUP) >> 3;   // first k-row-of-8 in this tile

        // ---- 8 chunks of k16 (fully unrolled: ptxas batches the 64 LDGs) ----
#pragma unroll
        for (int ch = 0; ch < 8; ch++) {
            const int* qr0 = qcol + (size_t)(qrow0 + 2 * ch) * N_DIM;
            const int* qr1 = qr0 + N_DIM;
            // W loads (4-lane broadcast each): rows {2ch, 2ch+1} x col offsets {0,8,16,24}
            uint32_t q00 = (uint32_t)qr0[0],  q01 = (uint32_t)qr0[8];
            uint32_t q02 = (uint32_t)qr0[16], q03 = (uint32_t)qr0[24];
            uint32_t q10 = (uint32_t)qr1[0],  q11 = (uint32_t)qr1[8];
            uint32_t q12 = (uint32_t)qr1[16], q13 = (uint32_t)qr1[24];

            // a-frags (dequant straight into fragment registers)
            uint32_t a[2][4];
            a[0][0] = dq2(q00, sh, mask, cm2, ca2, s2[0]);  // row n,    k pair j
            a[0][1] = dq2(q01, sh, mask, cm2, ca2, s2[1]);  // row n+8
            a[0][2] = dq2(q10, sh, mask, cm2, ca2, s2[0]);  // row n,    k pair j+8
            a[0][3] = dq2(q11, sh, mask, cm2, ca2, s2[1]);  // row n+8
            a[1][0] = dq2(q02, sh, mask, cm2, ca2, s2[2]);
            a[1][1] = dq2(q03, sh, mask, cm2, ca2, s2[3]);
            a[1][2] = dq2(q12, sh, mask, cm2, ca2, s2[2]);
            a[1][3] = dq2(q13, sh, mask, cm2, ca2, s2[3]);

            // b-frags: permuted-k pairs, m = 8t + lane4, pair j = lane&3
            const half* bb = &as2[buf][(size_t)(ch * 16 + (lane & 3) * 2)];
            uint32_t b[4][2];
#pragma unroll
            for (int t = 0; t < 4; t++) {
                const half* bp = bb + (size_t)(8 * t + lane4) * APITCH;
                b[t][0] = *reinterpret_cast<const uint32_t*>(bp);       // octet 2ch
                b[t][1] = *reinterpret_cast<const uint32_t*>(bp + 8);   // octet 2ch+1
            }

#pragma unroll
            for (int f = 0; f < 2; f++)
#pragma unroll
                for (int t = 0; t < 4; t++)
                    mma_16816(acc[f][t][0], acc[f][t][1], acc[f][t][2], acc[f][t][3],
                              a[f][0], a[f][1], a[f][2], a[f][3], b[t][0], b[t][1]);
        }
    }

    // ---- epilogue: write split partials, D[n][m] frag -> partial[split][m][n] ----
    float* pbase = g_partial + (size_t)split * M_DIM * N_DIM;
#pragma unroll
    for (int f = 0; f < 2; f++) {
        const int n_r = nbase + warp * 32 + 16 * f + lane4;
#pragma unroll
        for (int t = 0; t < 4; t++) {
            const int m_c = 8 * t + 2 * (lane & 3);
            float* p = pbase + (size_t)m_c * N_DIM + n_r;
            p[0]         = acc[f][t][0];   // (n_r,   m_c)
            p[N_DIM]     = acc[f][t][1];   // (n_r,   m_c+1)
            p[8]         = acc[f][t][2];   // (n_r+8, m_c)
            p[N_DIM + 8] = acc[f][t][3];   // (n_r+8, m_c+1)
        }
    }
}

// float2 per thread: 131072 threads (512 CTAs, ~3.5/SM) each with 8 independent
// LDG.64 -> 2x the concurrent load-chains of the float4 version, half the L1
// wavefronts per load. Perfectly coalesced (consecutive threads -> consecutive 8B).
__global__ void __launch_bounds__(256)
marlin_w4a16_reduce(const float* __restrict__ bias, float* __restrict__ out) {
    const int v = blockIdx.x * 256 + threadIdx.x;   // float2 index, n fastest
    const int e = v * 2;
    const int n = e & (N_DIM - 1);
    float2 s = make_float2(0.f, 0.f);
#pragma unroll
    for (int sp = 0; sp < SPLITS; sp++) {
        float2 p = *reinterpret_cast<const float2*>(
            &g_partial[(size_t)sp * (M_DIM * N_DIM) + e]);
        s.x += p.x; s.y += p.y;
    }
    float2 b = *reinterpret_cast<const float2*>(bias + n);
    s.x += b.x; s.y += b.y;
    *reinterpret_cast<float2*>(out + e) = s;
}

extern "C" void kernel_launch(void* const* d_in, const int* in_sizes, int n_in,
                              void* d_out, int out_size) {
    const float* A      = (const float*)d_in[0];
    const int*   qw     = (const int*)d_in[1];
    const float* scales = (const float*)d_in[2];
    const float* bias   = (const float*)d_in[3];
    float* out = (float*)d_out;

    dim3 grid(NTILES, SPLITS);
    marlin_w4a16_main<<<grid, THREADS>>>(A, qw, scales);
    marlin_w4a16_reduce<<<(M_DIM * N_DIM) / (256 * 2), 256>>>(bias, out);
}